// round 2
// baseline (speedup 1.0000x reference)
#include <cuda_runtime.h>
#include <math.h>

#define N_Q   8192
#define M_KV  8192
#define DIM   256
#define KNB   32
#define TAU_F 0.07f
#define EPS_F 1e-8f

#define BM 128
#define BN 128
#define BK 16
#define SST  132   // Bs row stride (floats)
#define SSTA 264   // As row stride (floats, duplicated pairs: 2*128 + 8 pad)

// scratch (device globals: allocation-free per harness rules)
__device__ float g_F[16384 * 256];                 // 16 MB  features pre-norm
__device__ float g_fxn[8192 * 256];                // 8 MB   normalized x-features, row-major
__device__ float g_fynT[256 * 8192];               // 8 MB   normalized y-features, TRANSPOSED [D][M]
__device__ float g_sim[(size_t)8192 * 8192];       // 256 MB similarity matrix

typedef unsigned long long u64;
typedef unsigned int u32;

__device__ __forceinline__ u64 dup2(float f) {
    u64 r; asm("mov.b64 %0, {%1, %1};" : "=l"(r) : "f"(f)); return r;
}
__device__ __forceinline__ void unpk2(u64 p, float& lo, float& hi) {
    asm("mov.b64 {%0, %1}, %2;" : "=f"(lo), "=f"(hi) : "l"(p));
}
// packed fp32x2 FMA: 2 FMA lanes per instruction (ptxas never auto-fuses this)
__device__ __forceinline__ void ffma2(u64& d, u64 a, u64 b) {
    asm("fma.rn.f32x2 %0, %1, %2, %0;" : "+l"(d) : "l"(a), "l"(b));
}

// ---------------------------------------------------------------------------
// Kernel 1: F = [x;y] @ W^T + b   (M=16384, N=256, K=256), fp32 via f32x2
// ---------------------------------------------------------------------------
__global__ __launch_bounds__(256, 2)
void feat_gemm_kernel(const float* __restrict__ x, const float* __restrict__ y,
                      const float* __restrict__ W, const float* __restrict__ bias)
{
    __shared__ float As[BK * SSTA];   // duplicated pairs: As[k][2r],As[k][2r+1] = A[r][k]
    __shared__ float Bs[BK * SST];
    const int tid = threadIdx.x;
    const int tr  = tid >> 4;          // 0..15, 8 rows each
    const int tc  = tid & 15;          // 0..15, 8 cols each
    const int r0  = blockIdx.y * BM;
    const int c0  = blockIdx.x * BN;

    u64 acc[8][4];
#pragma unroll
    for (int i = 0; i < 8; i++)
#pragma unroll
        for (int j = 0; j < 4; j++) acc[i][j] = 0ull;

    for (int k0 = 0; k0 < DIM; k0 += BK) {
        // A tile: Z[r0..+128][k0..+16]  -> As[k][2r..2r+1] duplicated
#pragma unroll
        for (int ld = 0; ld < 2; ld++) {
            int pos = tid + ld * 256;          // 0..511
            int r   = pos >> 2;                // 0..127
            int kg  = pos & 3;                 // float4 group in k
            int gr  = r0 + r;
            const float* src = (gr < N_Q) ? (x + (size_t)gr * DIM)
                                          : (y + (size_t)(gr - N_Q) * DIM);
            float4 v = *(const float4*)(src + k0 + kg * 4);
            *(u64*)(As + (kg * 4 + 0) * SSTA + 2 * r) = dup2(v.x);
            *(u64*)(As + (kg * 4 + 1) * SSTA + 2 * r) = dup2(v.y);
            *(u64*)(As + (kg * 4 + 2) * SSTA + 2 * r) = dup2(v.z);
            *(u64*)(As + (kg * 4 + 3) * SSTA + 2 * r) = dup2(v.w);
        }
        // B tile: Bs[k][c] = W[c0+c][k0+k]  (W row-major [D][D])
#pragma unroll
        for (int ld = 0; ld < 2; ld++) {
            int pos = tid + ld * 256;
            int c   = pos >> 2;                // 0..127
            int kg  = pos & 3;
            float4 v = *(const float4*)(W + (size_t)(c0 + c) * DIM + k0 + kg * 4);
            Bs[(kg * 4 + 0) * SST + c] = v.x;
            Bs[(kg * 4 + 1) * SST + c] = v.y;
            Bs[(kg * 4 + 2) * SST + c] = v.z;
            Bs[(kg * 4 + 3) * SST + c] = v.w;
        }
        __syncthreads();
#pragma unroll
        for (int kk = 0; kk < BK; kk++) {
            const u64* ap = (const u64*)(As + kk * SSTA) + tr * 8;
            const u64* bp = (const u64*)(Bs + kk * SST + tc * 8);
            u64 b0 = bp[0], b1 = bp[1], b2 = bp[2], b3 = bp[3];
#pragma unroll
            for (int i = 0; i < 8; i++) {
                u64 ai = ap[i];
                ffma2(acc[i][0], ai, b0);
                ffma2(acc[i][1], ai, b1);
                ffma2(acc[i][2], ai, b2);
                ffma2(acc[i][3], ai, b3);
            }
        }
        __syncthreads();
    }

    float bl[8];
#pragma unroll
    for (int u = 0; u < 8; u++) bl[u] = bias[c0 + tc * 8 + u];
#pragma unroll
    for (int i = 0; i < 8; i++) {
        int row = r0 + tr * 8 + i;
        float* dst = g_F + (size_t)row * DIM + c0 + tc * 8;
        float4 w0, w1;
        unpk2(acc[i][0], w0.x, w0.y); unpk2(acc[i][1], w0.z, w0.w);
        unpk2(acc[i][2], w1.x, w1.y); unpk2(acc[i][3], w1.z, w1.w);
        w0.x += bl[0]; w0.y += bl[1]; w0.z += bl[2]; w0.w += bl[3];
        w1.x += bl[4]; w1.y += bl[5]; w1.z += bl[6]; w1.w += bl[7];
        *(float4*)dst       = w0;
        *(float4*)(dst + 4) = w1;
    }
}

// ---------------------------------------------------------------------------
// Kernel 2: L2-normalize each row of F. x-rows -> g_fxn (row major),
//           y-rows -> g_fynT (transposed [D][M] for coalesced GEMM B loads)
// ---------------------------------------------------------------------------
__global__ __launch_bounds__(256)
void normalize_kernel()
{
    const int row = blockIdx.x;
    const int t   = threadIdx.x;          // 0..255 == feature index
    float v = g_F[(size_t)row * DIM + t];
    float sq = v * v;
#pragma unroll
    for (int o = 16; o > 0; o >>= 1) sq += __shfl_xor_sync(0xffffffffu, sq, o);
    __shared__ float ws[8];
    __shared__ float sres;
    if ((t & 31) == 0) ws[t >> 5] = sq;
    __syncthreads();
    if (t < 32) {
        float total = (t < 8) ? ws[t] : 0.0f;
#pragma unroll
        for (int o = 4; o > 0; o >>= 1) total += __shfl_xor_sync(0xffffffffu, total, o);
        if (t == 0) sres = rsqrtf(total + EPS_F);
    }
    __syncthreads();
    float s = sres;
    float o = v * s;
    if (row < N_Q) g_fxn[(size_t)row * DIM + t] = o;
    else           g_fynT[(size_t)t * M_KV + (row - N_Q)] = o;
}

// ---------------------------------------------------------------------------
// Kernel 3: sim = fxn @ fynT   (8192 x 8192 x 256), fp32 via f32x2
// ---------------------------------------------------------------------------
__global__ __launch_bounds__(256, 2)
void sim_gemm_kernel()
{
    __shared__ float As[BK * SSTA];
    __shared__ float Bs[BK * SST];
    const int tid = threadIdx.x;
    const int tr  = tid >> 4;
    const int tc  = tid & 15;
    const int r0  = blockIdx.y * BM;
    const int c0  = blockIdx.x * BN;

    u64 acc[8][4];
#pragma unroll
    for (int i = 0; i < 8; i++)
#pragma unroll
        for (int j = 0; j < 4; j++) acc[i][j] = 0ull;

    for (int k0 = 0; k0 < DIM; k0 += BK) {
        // A tile (g_fxn, row-major) -> As[k][2r..2r+1] duplicated
#pragma unroll
        for (int ld = 0; ld < 2; ld++) {
            int pos = tid + ld * 256;
            int r   = pos >> 2;
            int kg  = pos & 3;
            float4 v = *(const float4*)(g_fxn + (size_t)(r0 + r) * DIM + k0 + kg * 4);
            *(u64*)(As + (kg * 4 + 0) * SSTA + 2 * r) = dup2(v.x);
            *(u64*)(As + (kg * 4 + 1) * SSTA + 2 * r) = dup2(v.y);
            *(u64*)(As + (kg * 4 + 2) * SSTA + 2 * r) = dup2(v.z);
            *(u64*)(As + (kg * 4 + 3) * SSTA + 2 * r) = dup2(v.w);
        }
        // B tile (g_fynT, [D][M] row-major: k-rows contiguous in cols) -> Bs[k][c]
#pragma unroll
        for (int ld = 0; ld < 2; ld++) {
            int pos = tid + ld * 256;
            int k   = pos >> 5;                // 0..15
            int cg  = pos & 31;                // 32 float4 groups cover 128 cols
            float4 v = *(const float4*)(g_fynT + (size_t)(k0 + k) * M_KV + c0 + cg * 4);
            *(float4*)(Bs + k * SST + cg * 4) = v;
        }
        __syncthreads();
#pragma unroll
        for (int kk = 0; kk < BK; kk++) {
            const u64* ap = (const u64*)(As + kk * SSTA) + tr * 8;
            const u64* bp = (const u64*)(Bs + kk * SST + tc * 8);
            u64 b0 = bp[0], b1 = bp[1], b2 = bp[2], b3 = bp[3];
#pragma unroll
            for (int i = 0; i < 8; i++) {
                u64 ai = ap[i];
                ffma2(acc[i][0], ai, b0);
                ffma2(acc[i][1], ai, b1);
                ffma2(acc[i][2], ai, b2);
                ffma2(acc[i][3], ai, b3);
            }
        }
        __syncthreads();
    }
#pragma unroll
    for (int i = 0; i < 8; i++) {
        int row = r0 + tr * 8 + i;
        float* dst = g_sim + (size_t)row * M_KV + c0 + tc * 8;
        float4 w0, w1;
        unpk2(acc[i][0], w0.x, w0.y); unpk2(acc[i][1], w0.z, w0.w);
        unpk2(acc[i][2], w1.x, w1.y); unpk2(acc[i][3], w1.z, w1.w);
        *(float4*)dst       = w0;
        *(float4*)(dst + 4) = w1;
    }
}

// ---------------------------------------------------------------------------
// Kernel 4: exact top-32 per row via packed-key warpsort.
// key = (ord(val) << 32) | ~idx  — unsigned compare == (val desc, idx asc),
// matching jax.lax.top_k tie-breaking exactly.
// Stream with threshold filter + ballot/popc compaction into a per-warp smem
// buffer; every 32 survivors do one bitonic sort + bitonic top-k merge.
// ---------------------------------------------------------------------------
__device__ __forceinline__ u32 ordf(float f) {
    u32 b = __float_as_uint(f);
    return (b & 0x80000000u) ? ~b : (b | 0x80000000u);
}
__device__ __forceinline__ float key_val(u64 k) {
    u32 o = (u32)(k >> 32);
    u32 b = (o & 0x80000000u) ? (o ^ 0x80000000u) : ~o;
    return __uint_as_float(b);
}
__device__ __forceinline__ u64 make_key(float v, int idx) {
    return ((u64)ordf(v) << 32) | (u32)(~(u32)idx);
}
__device__ __forceinline__ u64 kmax(u64 a, u64 b) { return a > b ? a : b; }
__device__ __forceinline__ u64 kmin(u64 a, u64 b) { return a < b ? a : b; }
__device__ __forceinline__ u64 shflx(u64 v, int m) {
    return __shfl_xor_sync(0xffffffffu, v, m);
}

// Sort c descending across the warp, then merge top-32 of (L ∪ c) into L
// (L kept sorted descending).
__device__ __forceinline__ void merge32(u64& L, u64 c, int lane)
{
#pragma unroll
    for (int k = 2; k <= 32; k <<= 1) {
#pragma unroll
        for (int j = k >> 1; j > 0; j >>= 1) {
            u64 o = shflx(c, j);
            bool lower = (lane & j) == 0;
            bool desc  = (lane & k) == 0;
            c = (lower == desc) ? kmax(c, o) : kmin(c, o);
        }
    }
    // reverse c (now ascending), pairwise max -> bitonic, 5-stage merge desc
    u64 cr = shflx(c, 31);
    L = kmax(L, cr);
#pragma unroll
    for (int j = 16; j > 0; j >>= 1) {
        u64 o = shflx(L, j);
        bool lower = (lane & j) == 0;
        L = lower ? kmax(L, o) : kmin(L, o);
    }
}

__global__ __launch_bounds__(256)
void topk_kernel(float* __restrict__ out, int out_size)
{
    __shared__ u64 sbuf[8][64];
    const unsigned FULL = 0xffffffffu;
    const int warp = threadIdx.x >> 5;
    const int lane = threadIdx.x & 31;
    const int row  = blockIdx.x * 8 + warp;
    u64* buf = sbuf[warp];
    const float* rp = g_sim + (size_t)row * M_KV;

    u64   list = (u64)ordf(-3.0e38f) << 32;   // 32 sentinels, sorted (all equal)
    float mn   = -3.0e38f;
    int   cnt  = 0;

    for (int base = 0; base < M_KV; base += 128) {
        float4 v4 = *(const float4*)(rp + base + lane * 4);
        float c[4] = {v4.x, v4.y, v4.z, v4.w};
#pragma unroll
        for (int q = 0; q < 4; q++) {
            unsigned bal = __ballot_sync(FULL, c[q] > mn);
            if (bal) {
                bool mine = (c[q] > mn);
                int pos = cnt + __popc(bal & ((1u << lane) - 1));
                if (mine) buf[pos] = make_key(c[q], base + lane * 4 + q);
                cnt += __popc(bal);
                while (cnt >= 32) {
                    __syncwarp();
                    u64 cd = buf[lane];
                    if (lane < cnt - 32) buf[lane] = buf[32 + lane];
                    __syncwarp();
                    cnt -= 32;
                    merge32(list, cd, lane);
                    mn = key_val(__shfl_sync(FULL, list, 31));
                }
            }
        }
    }
    if (cnt > 0) {
        __syncwarp();
        u64 cd = (lane < cnt) ? buf[lane] : 0ull;   // key 0 < every real key
        merge32(list, cd, lane);
    }

    // decode + temperature softmax over the 32 (list sorted desc by key)
    float v   = key_val(list);
    int   idx = (int)(~(u32)list);
    float top = __shfl_sync(FULL, v, 0);
    float e = expf((v - top) / TAU_F);
    float s = e;
#pragma unroll
    for (int o = 16; o > 0; o >>= 1) s += __shfl_xor_sync(FULL, s, o);
    float soft = e / s;

    out[(size_t)row * KNB + lane] = soft;
    if (out_size >= 2 * N_Q * KNB)
        out[(size_t)N_Q * KNB + (size_t)row * KNB + lane] = (float)idx;
}

// ---------------------------------------------------------------------------
extern "C" void kernel_launch(void* const* d_in, const int* in_sizes, int n_in,
                              void* d_out, int out_size)
{
    const float* x = (const float*)d_in[0];
    const float* y = (const float*)d_in[1];
    const float* W = (const float*)d_in[2];
    const float* b = (const float*)d_in[3];
    float* out = (float*)d_out;
    (void)in_sizes; (void)n_in;

    feat_gemm_kernel<<<dim3(DIM / BN, (N_Q + M_KV) / BM), 256>>>(x, y, W, b);
    normalize_kernel<<<N_Q + M_KV, 256>>>();
    sim_gemm_kernel<<<dim3(M_KV / BN, N_Q / BM), 256>>>();
    topk_kernel<<<N_Q / 8, 256>>>(out, out_size);
}